// round 9
// baseline (speedup 1.0000x reference)
#include <cuda_runtime.h>
#include <cstdint>

#define VM_D        16
#define VM_NINC     1000
#define VM_BLOCK    640
#define VM_CTAS     148
#define VM_UNROLL   5
#define VM_TABLE_BYTES (VM_D * VM_NINC * 8)   // 128 KB: float2 (grid, inc) per bin

__device__ __forceinline__ void vm_process(const float4 yv,
                                           const float2* __restrict__ pb,
                                           float4& xv, float& fac)
{
    const float ninc_f = (float)VM_NINC;
    // y in [0,1): iy = floor(y*1000) <= 999 always (max fp32 y*1000 = 999.99994).
    // min() kept only as an OOB-safety guard; dy in [0,1) by construction.
    {
        float t = yv.x * ninc_f;
        int   iy = min(__float2int_rd(t), VM_NINC - 1);
        float dy = t - (float)iy;
        float2 p = pb[iy];
        xv.x = fmaf(p.y, dy, p.x);
        fac  = p.y * ninc_f;
    }
    {
        float t = yv.y * ninc_f;
        int   iy = min(__float2int_rd(t), VM_NINC - 1);
        float dy = t - (float)iy;
        float2 p = pb[VM_NINC + iy];
        xv.y = fmaf(p.y, dy, p.x);
        fac *= p.y * ninc_f;
    }
    {
        float t = yv.z * ninc_f;
        int   iy = min(__float2int_rd(t), VM_NINC - 1);
        float dy = t - (float)iy;
        float2 p = pb[2 * VM_NINC + iy];
        xv.z = fmaf(p.y, dy, p.x);
        fac *= p.y * ninc_f;
    }
    {
        float t = yv.w * ninc_f;
        int   iy = min(__float2int_rd(t), VM_NINC - 1);
        float dy = t - (float)iy;
        float2 p = pb[3 * VM_NINC + iy];
        xv.w = fmaf(p.y, dy, p.x);
        fac *= p.y * ninc_f;
    }
}

__global__ __launch_bounds__(VM_BLOCK, 1)
void vegas_map_kernel(const float* __restrict__ y,
                      const float* __restrict__ grid,
                      const float* __restrict__ inc,
                      float* __restrict__ x_out,
                      float* __restrict__ jac_out,
                      int n_f4)
{
    extern __shared__ unsigned char smem_raw[];
    float2* __restrict__ pairs = reinterpret_cast<float2*>(smem_raw);

    const int tid = threadIdx.x;

    const float4* __restrict__ y4 = reinterpret_cast<const float4*>(y);
    float4* __restrict__       x4 = reinterpret_cast<float4*>(x_out);

    const int stride  = VM_CTAS * VM_BLOCK;      // 94720
    const int step    = stride * VM_UNROLL;
    const int i0      = blockIdx.x * VM_BLOCK + tid;
    const int jstride = stride >> 2;             // jac index stride per u-slot

    int i = i0;
    int j = i0 >> 2;
    bool have = (i + (VM_UNROLL - 1) * stride < n_f4);

    // ---- Issue first y prefetch batch BEFORE the table fill: DRAM latency
    //      of these loads overlaps with the (L2-bound) table fill below.
    float4 cur[VM_UNROLL];
    if (have) {
        #pragma unroll
        for (int u = 0; u < VM_UNROLL; ++u) cur[u] = __ldg(y4 + i + u * stride);
    }

    // ---- Fill interleaved (grid, inc) table into shared memory.
    //      inc rows are 1000 floats (16B-aligned): load as float4.
    {
        const float4* __restrict__ inc4 = reinterpret_cast<const float4*>(inc);
        // 16 dims * 250 float4 = 4000 float4 elements total
        for (int t = tid; t < VM_D * (VM_NINC / 4); t += VM_BLOCK) {
            const int d  = t / (VM_NINC / 4);
            const int k4 = t - d * (VM_NINC / 4);
            const int i4 = k4 * 4;
            const float4 h4 = __ldg(inc4 + t);
            const float* grow = grid + d * (VM_NINC + 1) + i4;
            float2* __restrict__ dst = pairs + d * VM_NINC + i4;
            dst[0] = make_float2(__ldg(grow + 0), h4.x);
            dst[1] = make_float2(__ldg(grow + 1), h4.y);
            dst[2] = make_float2(__ldg(grow + 2), h4.z);
            dst[3] = make_float2(__ldg(grow + 3), h4.w);
        }
    }
    __syncthreads();

    // Thread owns 4 dims [4q..4q+3]; quad of threads covers one sample.
    const int q = tid & 3;
    const float2* __restrict__ pb = pairs + q * 4 * VM_NINC;

    // ---- Software-pipelined main loop: prefetch batch k+1 before processing batch k ----
    while (have) {
        const int inext = i + step;
        const bool have_next = (inext + (VM_UNROLL - 1) * stride < n_f4);

        float4 nxt[VM_UNROLL];
        if (have_next) {
            #pragma unroll
            for (int u = 0; u < VM_UNROLL; ++u) nxt[u] = __ldg(y4 + inext + u * stride);
        }

        #pragma unroll
        for (int u = 0; u < VM_UNROLL; ++u) {
            float4 xv;
            float fac;
            vm_process(cur[u], pb, xv, fac);

            x4[i + u * stride] = xv;

            fac *= __shfl_xor_sync(0xFFFFFFFFu, fac, 1);
            fac *= __shfl_xor_sync(0xFFFFFFFFu, fac, 2);
            if (q == 0) {
                jac_out[j + u * jstride] = fac;
            }
        }

        #pragma unroll
        for (int u = 0; u < VM_UNROLL; ++u) cur[u] = nxt[u];
        i = inext;
        j += step >> 2;
        have = have_next;
    }

    // ---- Remainder: single-iteration strided loop ----
    for (; i < n_f4; i += stride) {
        const float4 yv = __ldg(y4 + i);
        float4 xv;
        float fac;
        vm_process(yv, pb, xv, fac);

        x4[i] = xv;

        fac *= __shfl_xor_sync(0xFFFFFFFFu, fac, 1);
        fac *= __shfl_xor_sync(0xFFFFFFFFu, fac, 2);
        if (q == 0) {
            jac_out[i >> 2] = fac;
        }
    }
}

extern "C" void kernel_launch(void* const* d_in, const int* in_sizes, int n_in,
                              void* d_out, int out_size)
{
    const float* y    = (const float*)d_in[0];
    const float* grid = (const float*)d_in[1];
    const float* inc  = (const float*)d_in[2];

    const int B = in_sizes[0] / VM_D;               // 1,048,576
    float* x   = (float*)d_out;                     // [B,16]
    float* jac = (float*)d_out + (size_t)B * VM_D;  // [B]

    const int n_f4 = B * (VM_D / 4);                // 4,194,304

    cudaFuncSetAttribute(vegas_map_kernel,
                         cudaFuncAttributeMaxDynamicSharedMemorySize,
                         (int)VM_TABLE_BYTES);

    vegas_map_kernel<<<VM_CTAS, VM_BLOCK, VM_TABLE_BYTES>>>(y, grid, inc, x, jac, n_f4);
}

// round 10
// speedup vs baseline: 1.0899x; 1.0899x over previous
#include <cuda_runtime.h>
#include <cstdint>

#define VM_D        16
#define VM_NINC     1000
#define VM_BLOCK    768
#define VM_CTAS     148
#define VM_UNROLL   4
#define VM_TABLE_BYTES (VM_D * VM_NINC * 8)   // 128 KB: float2 (grid, inc) per bin

__device__ __forceinline__ void vm_process(const float4 yv,
                                           const float2* __restrict__ pb,
                                           float4& xv, float& fac)
{
    const float ninc_f = (float)VM_NINC;
    // y in [0,1): iy = floor(y*1000) <= 999 always (max fp32 y*1000 = 999.99994).
    // min() kept only as an OOB-safety guard; dy in [0,1) by construction.
    {
        float t = yv.x * ninc_f;
        int   iy = min(__float2int_rd(t), VM_NINC - 1);
        float dy = t - (float)iy;
        float2 p = pb[iy];
        xv.x = fmaf(p.y, dy, p.x);
        fac  = p.y * ninc_f;
    }
    {
        float t = yv.y * ninc_f;
        int   iy = min(__float2int_rd(t), VM_NINC - 1);
        float dy = t - (float)iy;
        float2 p = pb[VM_NINC + iy];
        xv.y = fmaf(p.y, dy, p.x);
        fac *= p.y * ninc_f;
    }
    {
        float t = yv.z * ninc_f;
        int   iy = min(__float2int_rd(t), VM_NINC - 1);
        float dy = t - (float)iy;
        float2 p = pb[2 * VM_NINC + iy];
        xv.z = fmaf(p.y, dy, p.x);
        fac *= p.y * ninc_f;
    }
    {
        float t = yv.w * ninc_f;
        int   iy = min(__float2int_rd(t), VM_NINC - 1);
        float dy = t - (float)iy;
        float2 p = pb[3 * VM_NINC + iy];
        xv.w = fmaf(p.y, dy, p.x);
        fac *= p.y * ninc_f;
    }
}

__global__ __launch_bounds__(VM_BLOCK, 1)
void vegas_map_kernel(const float* __restrict__ y,
                      const float* __restrict__ grid,
                      const float* __restrict__ inc,
                      float* __restrict__ x_out,
                      float* __restrict__ jac_out,
                      int n_f4)
{
    extern __shared__ unsigned char smem_raw[];
    float2* __restrict__ pairs = reinterpret_cast<float2*>(smem_raw);

    const int tid = threadIdx.x;

    const float4* __restrict__ y4 = reinterpret_cast<const float4*>(y);
    float4* __restrict__       x4 = reinterpret_cast<float4*>(x_out);

    const int stride  = VM_CTAS * VM_BLOCK;      // 113664
    const int step    = stride * VM_UNROLL;
    const int i0      = blockIdx.x * VM_BLOCK + tid;
    const int jstride = stride >> 2;             // jac index stride per u-slot

    int i = i0;
    int j = i0 >> 2;
    bool have = (i + (VM_UNROLL - 1) * stride < n_f4);

    // ---- Issue first y prefetch batch BEFORE the table fill: DRAM latency
    //      of these loads overlaps with the (L2-bound) table fill below.
    float4 cur[VM_UNROLL];
    if (have) {
        #pragma unroll
        for (int u = 0; u < VM_UNROLL; ++u) cur[u] = __ldcs(y4 + i + u * stride);
    }

    // ---- Fill interleaved (grid, inc) table into shared memory.
    //      Both loops read GMEM fully coalesced (contiguous scalar loads).
    {
        // inc[t] maps 1:1 onto pairs[t].y (both are [16][1000] row-major).
        float* __restrict__ ph = reinterpret_cast<float*>(smem_raw) + 1;
        for (int t = tid; t < VM_D * VM_NINC; t += VM_BLOCK) {
            ph[2 * t] = __ldg(inc + t);
        }
        // grid is [16][1001]; drop each row's last element (right edge unused:
        // iy <= 999 always), scatter the rest into pairs[.].x.
        float* __restrict__ pg = reinterpret_cast<float*>(smem_raw);
        for (int t = tid; t < VM_D * (VM_NINC + 1); t += VM_BLOCK) {
            float v = __ldg(grid + t);
            int d = t / (VM_NINC + 1);
            int k = t - d * (VM_NINC + 1);
            if (k < VM_NINC) {
                pg[2 * (d * VM_NINC + k)] = v;
            }
        }
    }
    __syncthreads();

    // Thread owns 4 dims [4q..4q+3]; quad of threads covers one sample.
    const int q = tid & 3;
    const float2* __restrict__ pb = pairs + q * 4 * VM_NINC;

    // ---- Software-pipelined main loop: prefetch batch k+1 before processing batch k ----
    while (have) {
        const int inext = i + step;
        const bool have_next = (inext + (VM_UNROLL - 1) * stride < n_f4);

        float4 nxt[VM_UNROLL];
        if (have_next) {
            #pragma unroll
            for (int u = 0; u < VM_UNROLL; ++u) nxt[u] = __ldcs(y4 + inext + u * stride);
        }

        #pragma unroll
        for (int u = 0; u < VM_UNROLL; ++u) {
            float4 xv;
            float fac;
            vm_process(cur[u], pb, xv, fac);

            __stcs(x4 + i + u * stride, xv);

            fac *= __shfl_xor_sync(0xFFFFFFFFu, fac, 1);
            fac *= __shfl_xor_sync(0xFFFFFFFFu, fac, 2);
            if (q == 0) {
                __stcs(jac_out + j + u * jstride, fac);
            }
        }

        #pragma unroll
        for (int u = 0; u < VM_UNROLL; ++u) cur[u] = nxt[u];
        i = inext;
        j += step >> 2;
        have = have_next;
    }

    // ---- Remainder: single-iteration strided loop ----
    for (; i < n_f4; i += stride) {
        const float4 yv = __ldcs(y4 + i);
        float4 xv;
        float fac;
        vm_process(yv, pb, xv, fac);

        __stcs(x4 + i, xv);

        fac *= __shfl_xor_sync(0xFFFFFFFFu, fac, 1);
        fac *= __shfl_xor_sync(0xFFFFFFFFu, fac, 2);
        if (q == 0) {
            __stcs(jac_out + (i >> 2), fac);
        }
    }
}

extern "C" void kernel_launch(void* const* d_in, const int* in_sizes, int n_in,
                              void* d_out, int out_size)
{
    const float* y    = (const float*)d_in[0];
    const float* grid = (const float*)d_in[1];
    const float* inc  = (const float*)d_in[2];

    const int B = in_sizes[0] / VM_D;               // 1,048,576
    float* x   = (float*)d_out;                     // [B,16]
    float* jac = (float*)d_out + (size_t)B * VM_D;  // [B]

    const int n_f4 = B * (VM_D / 4);                // 4,194,304

    cudaFuncSetAttribute(vegas_map_kernel,
                         cudaFuncAttributeMaxDynamicSharedMemorySize,
                         (int)VM_TABLE_BYTES);

    vegas_map_kernel<<<VM_CTAS, VM_BLOCK, VM_TABLE_BYTES>>>(y, grid, inc, x, jac, n_f4);
}